// round 15
// baseline (speedup 1.0000x reference)
#include <cuda_runtime.h>
#include <cuda_fp16.h>
#include <cstdint>

#define Hh 512
#define Bb 64
#define Ss 2048
#define BS (Bb*Ss)   // 131072 rows

// ---------------- device scratch (no cudaMalloc allowed) ----------------
__device__ __half g_ench[(size_t)BS*Hh];   // enc in fp16 (128 MB)
__device__ __half g_Wh[Hh*Hh];             // W_w in fp16
__device__ float g_ubb[Bb*Hh];             // u + U_b + W_b per (b,h)
__device__ float g_energy8[8*BS];          // per-coltile energy partials
__device__ float g_ctx[Bb*64*Hh];          // context partials (16 sc x 4 grp)

// ---------------- generic PTX helpers ----------------
__device__ __forceinline__ void cpasync16(uint32_t dst, const void* src) {
    asm volatile("cp.async.cg.shared.global [%0], [%1], 16;\n"
                 :: "r"(dst), "l"(src));
}
__device__ __forceinline__ void cp_commit() {
    asm volatile("cp.async.commit_group;\n" ::: "memory");
}
template<int N> __device__ __forceinline__ void cp_wait() {
    asm volatile("cp.async.wait_group %0;\n" :: "n"(N) : "memory");
}
__device__ __forceinline__ uint32_t smem_u32(const void* p) {
    uint32_t a;
    asm("{ .reg .u64 t; cvta.to.shared.u64 t, %1; cvt.u32.u64 %0, t; }"
        : "=r"(a) : "l"(p));
    return a;
}
__device__ __forceinline__ float tanh_ap(float x) {
    float y;
    asm("tanh.approx.f32 %0, %1;" : "=f"(y) : "f"(x));
    return y;
}
__device__ __forceinline__ void ldsm_x4(uint32_t* r, uint32_t addr) {
    asm volatile("ldmatrix.sync.aligned.m8n8.x4.shared.b16 {%0,%1,%2,%3}, [%4];"
                 : "=r"(r[0]), "=r"(r[1]), "=r"(r[2]), "=r"(r[3]) : "r"(addr));
}
__device__ __forceinline__ void mma_f16(float* c, const uint32_t* a,
                                        uint32_t b0, uint32_t b1) {
    asm volatile(
        "mma.sync.aligned.m16n8k16.row.col.f32.f16.f16.f32 "
        "{%0,%1,%2,%3}, {%4,%5,%6,%7}, {%8,%9}, {%0,%1,%2,%3};"
        : "+f"(c[0]), "+f"(c[1]), "+f"(c[2]), "+f"(c[3])
        : "r"(a[0]), "r"(a[1]), "r"(a[2]), "r"(a[3]), "r"(b0), "r"(b1));
}

// SMEM per CTA (dynamic, 96KB):
//   A16: 4 stages x 16KB  [blk4][row128][32B, 16B-pair xor (r>>2)&1]
//   B16: 4 stages x 8KB   [blk4][n64][32B, xor]
#define SMA_STAGE 16384u
#define SMB_OFF   65536u
#define SMB_STAGE 8192u
#define SMEM_TOTAL (65536 + 4*8192)   // 98304

// ---------------- converts ----------------
__global__ void k_cvt_enc(const float* __restrict__ enc) {
    size_t i = ((size_t)blockIdx.x*blockDim.x + threadIdx.x) * 8;
    const float4* s = reinterpret_cast<const float4*>(enc + i);
    float4 v0 = s[0], v1 = s[1];
    __half2 h[4];
    h[0] = __floats2half2_rn(v0.x, v0.y);
    h[1] = __floats2half2_rn(v0.z, v0.w);
    h[2] = __floats2half2_rn(v1.x, v1.y);
    h[3] = __floats2half2_rn(v1.z, v1.w);
    *reinterpret_cast<uint4*>(g_ench + i) = *reinterpret_cast<uint4*>(h);
}
__global__ void k_cvt_W(const float* __restrict__ W) {
    size_t i = ((size_t)blockIdx.x*blockDim.x + threadIdx.x) * 8;
    const float4* s = reinterpret_cast<const float4*>(W + i);
    float4 v0 = s[0], v1 = s[1];
    __half2 h[4];
    h[0] = __floats2half2_rn(v0.x, v0.y);
    h[1] = __floats2half2_rn(v0.z, v0.w);
    h[2] = __floats2half2_rn(v1.x, v1.y);
    h[3] = __floats2half2_rn(v1.z, v1.w);
    *reinterpret_cast<uint4*>(g_Wh + i) = *reinterpret_cast<uint4*>(h);
}

// ---------------- prep: ubb = U(h) + U_b + W_b ----------------
__global__ void k_ubb(const float* __restrict__ hid,
                      const float* __restrict__ Uw,
                      const float* __restrict__ Ub,
                      const float* __restrict__ Wb) {
    int b = blockIdx.x;
    int h = threadIdx.x;
    __shared__ float hs[Hh];
    hs[h] = hid[b*Hh + h];
    __syncthreads();
    const float4* row = reinterpret_cast<const float4*>(Uw + (size_t)h*Hh);
    const float4* hv  = reinterpret_cast<const float4*>(hs);
    float acc = 0.f;
    #pragma unroll 4
    for (int k = 0; k < Hh/4; k++) {
        float4 r = row[k]; float4 x = hv[k];
        acc += r.x*x.x + r.y*x.y + r.z*x.z + r.w*x.w;
    }
    g_ubb[b*Hh + h] = acc + Ub[h] + Wb[h];
}

// ---------------- main: fp16 mma, 4-stage wait<2> single-sync pipeline ----------------
// CTA M128xN64, 256 threads / 8 warps, 2 CTAs/SM.
// grid (8 coltiles, 1024 rowtiles): 8 launch-adjacent CTAs share the A tile in L2,
// W (512KB fp16) stays fully L2-resident.

__device__ __forceinline__ void load_chunk(uint32_t sb, int row0, int col0,
                                           int kc, int stage, int tid) {
    uint32_t abase = sb + (uint32_t)stage * SMA_STAGE;
    uint32_t bbase = sb + SMB_OFF + (uint32_t)stage * SMB_STAGE;
    #pragma unroll
    for (int i = 0; i < 4; i++) {            // A: 1024 x 16B
        int u = tid + i*256;
        int blk = u >> 8, v = u & 255, r = v >> 1, c16 = v & 1;
        int p16 = c16 ^ ((r >> 2) & 1);
        cpasync16(abase + (uint32_t)(blk*4096 + r*32 + p16*16),
                  g_ench + (size_t)(row0 + r)*Hh + kc + blk*16 + c16*8);
    }
    #pragma unroll
    for (int i = 0; i < 2; i++) {            // B: 512 x 16B (64 n-rows)
        int u = tid + i*256;
        int blk = u >> 7, v = u & 127, n = v >> 1, c16 = v & 1;
        int p16 = c16 ^ ((n >> 2) & 1);
        cpasync16(bbase + (uint32_t)(blk*2048 + n*32 + p16*16),
                  g_Wh + (size_t)(col0 + n)*Hh + kc + blk*16 + c16*8);
    }
    cp_commit();
}

__global__ void __launch_bounds__(256, 2)
k_energy(const float* __restrict__ Vw) {
    extern __shared__ char smem[];
    uint32_t sb = smem_u32(smem);
    const int tid = threadIdx.x;
    const int wid = tid >> 5, lane = tid & 31;
    const int g = lane >> 2, tig = lane & 3;
    const int warp_m = wid & 3, warp_n = wid >> 2;
    const int m_base = warp_m * 32;
    const int n_base = warp_n * 32;

    const int col0 = blockIdx.x * 64;
    const int row0 = blockIdx.y * 128;       // never spans a batch
    const int b = row0 / Ss;

    // ldmatrix lane addresses (xor-swizzled 16B chunks in 32B rows)
    const int a_row = m_base + (lane & 15);
    const uint32_t a_sw = (uint32_t)(((lane >> 4) ^ (a_row >> 2)) & 1);
    const uint32_t a_off = (uint32_t)(a_row*32) + a_sw*16;
    const int b_nrow = n_base + (lane & 7) + ((lane >> 1) & 8);
    const uint32_t b_sw = (uint32_t)(((lane >> 3) ^ (b_nrow >> 2)) & 1);
    const uint32_t b_off = (uint32_t)(b_nrow*32) + b_sw*16;

    float c[2][4][4];
    #pragma unroll
    for (int mt = 0; mt < 2; mt++)
        #pragma unroll
        for (int nt = 0; nt < 4; nt++)
            #pragma unroll
            for (int j = 0; j < 4; j++) c[mt][nt][j] = 0.f;

    // prologue: chunks 0,1,2 in flight
    load_chunk(sb, row0, col0, 0,   0, tid);
    load_chunk(sb, row0, col0, 64,  1, tid);
    load_chunk(sb, row0, col0, 128, 2, tid);

    for (int ch = 0; ch < 8; ch++) {
        // groups in flight at top: chunks ch..min(ch+2,7)
        if (ch < 6)      cp_wait<2>();
        else if (ch < 7) cp_wait<1>();
        else             cp_wait<0>();
        __syncthreads();                     // chunk ch ready; MMA(ch-1) done by all

        // hoisted load: stage (ch+3)%4 == (ch-1)%4, last read by MMA(ch-1)
        if (ch + 3 < 8)
            load_chunk(sb, row0, col0, (ch + 3)*64, (ch + 3) & 3, tid);

        const uint32_t st = (uint32_t)(ch & 3);
        const uint32_t A16 = sb + st*SMA_STAGE;
        const uint32_t Bs  = sb + SMB_OFF + st*SMB_STAGE;

        #pragma unroll
        for (int blk = 0; blk < 4; blk++) {
            uint32_t a[2][4];
            ldsm_x4(a[0], A16 + blk*4096u + a_off);
            ldsm_x4(a[1], A16 + blk*4096u + a_off + 512u);
            uint32_t bf[4][2];
            #pragma unroll
            for (int p = 0; p < 2; p++) {
                uint32_t r[4];
                ldsm_x4(r, Bs + blk*2048u + b_off + (uint32_t)p*512u);
                bf[2*p][0]   = r[0]; bf[2*p][1]   = r[1];
                bf[2*p+1][0] = r[2]; bf[2*p+1][1] = r[3];
            }
            #pragma unroll
            for (int mt = 0; mt < 2; mt++)
                #pragma unroll
                for (int nt = 0; nt < 4; nt++)
                    mma_f16(c[mt][nt], a[mt], bf[nt][0], bf[nt][1]);
        }
    }

    // fused epilogue: partial energy over this CTA's 64 cols, combined in smem
    __syncthreads();
    float* s_e = reinterpret_cast<float*>(smem);
    if (tid < 128) s_e[tid] = 0.f;
    __syncthreads();

    float ub[4][2], vv[4][2];
    #pragma unroll
    for (int nt = 0; nt < 4; nt++) {
        int cb = col0 + n_base + nt*8 + 2*tig;
        ub[nt][0] = g_ubb[b*Hh + cb];     ub[nt][1] = g_ubb[b*Hh + cb + 1];
        vv[nt][0] = Vw[cb];               vv[nt][1] = Vw[cb + 1];
    }
    #pragma unroll
    for (int mt = 0; mt < 2; mt++) {
        float e0 = 0.f, e1 = 0.f;
        #pragma unroll
        for (int nt = 0; nt < 4; nt++) {
            e0 += vv[nt][0]*tanh_ap(c[mt][nt][0] + ub[nt][0]);
            e0 += vv[nt][1]*tanh_ap(c[mt][nt][1] + ub[nt][1]);
            e1 += vv[nt][0]*tanh_ap(c[mt][nt][2] + ub[nt][0]);
            e1 += vv[nt][1]*tanh_ap(c[mt][nt][3] + ub[nt][1]);
        }
        e0 += __shfl_xor_sync(0xffffffffu, e0, 1);
        e0 += __shfl_xor_sync(0xffffffffu, e0, 2);
        e1 += __shfl_xor_sync(0xffffffffu, e1, 1);
        e1 += __shfl_xor_sync(0xffffffffu, e1, 2);
        if (tig == 0) {
            atomicAdd(&s_e[m_base + mt*16 + g],     e0);
            atomicAdd(&s_e[m_base + mt*16 + g + 8], e1);
        }
    }
    __syncthreads();
    if (tid < 128)
        g_energy8[(size_t)blockIdx.x*BS + row0 + tid] = s_e[tid];
}

// ---------------- softmax over S per batch (sums 8 coltile slices) ----------------
__global__ void k_softmax(float* __restrict__ attn) {
    const int b = blockIdx.x;
    const int tid = threadIdx.x;             // 256
    __shared__ float red[256];
    float v[8];
    float mx = -1e30f;
    #pragma unroll
    for (int i = 0; i < 8; i++) {
        int idx = b*Ss + tid + i*256;
        float s = 0.f;
        #pragma unroll
        for (int t = 0; t < 8; t++) s += g_energy8[(size_t)t*BS + idx];
        v[i] = s;
        mx = fmaxf(mx, v[i]);
    }
    red[tid] = mx; __syncthreads();
    for (int o = 128; o > 0; o >>= 1) {
        if (tid < o) red[tid] = fmaxf(red[tid], red[tid+o]);
        __syncthreads();
    }
    mx = red[0]; __syncthreads();
    float sum = 0.f;
    #pragma unroll
    for (int i = 0; i < 8; i++) { v[i] = __expf(v[i] - mx); sum += v[i]; }
    red[tid] = sum; __syncthreads();
    for (int o = 128; o > 0; o >>= 1) {
        if (tid < o) red[tid] += red[tid+o];
        __syncthreads();
    }
    float inv = 1.f / red[0];
    #pragma unroll
    for (int i = 0; i < 8; i++)
        attn[b*Ss + tid + i*256] = v[i] * inv;
}

// ---------------- context = attn @ enc (fp16 enc, fp32 accumulate) ----------------
__global__ void k_ctx_part(const float* __restrict__ attn) {
    const int sc = blockIdx.x;               // 0..15
    const int b  = blockIdx.y;
    const int tid = threadIdx.x;             // 256 = 4 grp x 64
    const int grp = tid >> 6;
    const int h0 = (tid & 63) * 8;
    const int s0 = sc * 128;
    const float* ab = attn + b*Ss + s0;
    const __half* eb = g_ench + ((size_t)(b*Ss + s0))*Hh + h0;
    float acc[8] = {0.f,0.f,0.f,0.f,0.f,0.f,0.f,0.f};
    #pragma unroll 4
    for (int i = 0; i < 32; i++) {
        int s = i*4 + grp;
        float w = ab[s];
        uint4 raw = *reinterpret_cast<const uint4*>(eb + (size_t)s*Hh);
        const __half2* hp = reinterpret_cast<const __half2*>(&raw);
        #pragma unroll
        for (int j = 0; j < 4; j++) {
            float2 f = __half22float2(hp[j]);
            acc[2*j]   += w * f.x;
            acc[2*j+1] += w * f.y;
        }
    }
    float* dst = g_ctx + ((size_t)(b*64 + sc*4 + grp))*Hh + h0;
    #pragma unroll
    for (int j = 0; j < 8; j++) dst[j] = acc[j];
}

__global__ void k_ctx_reduce(float* __restrict__ ctx) {
    const int b = blockIdx.x;
    const int h = threadIdx.x;               // 512
    float s = 0.f;
    #pragma unroll
    for (int p = 0; p < 64; p++)
        s += g_ctx[((size_t)(b*64 + p))*Hh + h];
    ctx[b*Hh + h] = s;
}

// ---------------- launch ----------------
extern "C" void kernel_launch(void* const* d_in, const int* in_sizes, int n_in,
                              void* d_out, int out_size) {
    const float* hidden = (const float*)d_in[0];
    const float* enc    = (const float*)d_in[1];
    const float* U_w    = (const float*)d_in[2];
    const float* U_b    = (const float*)d_in[3];
    const float* W_w    = (const float*)d_in[4];
    const float* W_b    = (const float*)d_in[5];
    const float* V_w    = (const float*)d_in[6];
    // V_b shifts all energies equally -> softmax invariant -> unused.

    float* out_ctx  = (float*)d_out;            // [B,H]
    float* out_attn = out_ctx + Bb*Hh;          // [B,S]

    cudaFuncSetAttribute(k_energy,
                         cudaFuncAttributeMaxDynamicSharedMemorySize, SMEM_TOTAL);

    unsigned cvt_blocks = (unsigned)(((size_t)BS * Hh) / 8u / 256u);  // 32768
    k_cvt_enc<<<cvt_blocks, 256>>>(enc);
    k_cvt_W<<<Hh*Hh/8/256, 256>>>(W_w);
    k_ubb<<<Bb, Hh>>>(hidden, U_w, U_b, W_b);
    k_energy<<<dim3(8, BS/128), 256, SMEM_TOTAL>>>(V_w);
    k_softmax<<<Bb, 256>>>(out_attn);
    k_ctx_part<<<dim3(16, Bb), 256>>>(out_attn);
    k_ctx_reduce<<<Bb, Hh>>>(out_ctx);
}

// round 16
// speedup vs baseline: 1.0521x; 1.0521x over previous
#include <cuda_runtime.h>
#include <cuda_fp16.h>
#include <cstdint>

#define Hh 512
#define Bb 64
#define Ss 2048
#define BS (Bb*Ss)   // 131072 rows

// ---------------- device scratch (no cudaMalloc allowed) ----------------
__device__ __half g_ench[(size_t)BS*Hh];   // enc in fp16 (128 MB)
__device__ __half g_Wh[Hh*Hh];             // W_w in fp16
__device__ float g_ubb[Bb*Hh];             // u + U_b + W_b per (b,h)
__device__ float g_energy8[8*BS];          // per-coltile energy partials
__device__ float g_ctx[Bb*64*Hh];          // context partials (16 sc x 4 grp)

// ---------------- generic PTX helpers ----------------
__device__ __forceinline__ void cpasync16(uint32_t dst, const void* src) {
    asm volatile("cp.async.cg.shared.global [%0], [%1], 16;\n"
                 :: "r"(dst), "l"(src));
}
__device__ __forceinline__ void cp_commit() {
    asm volatile("cp.async.commit_group;\n" ::: "memory");
}
template<int N> __device__ __forceinline__ void cp_wait() {
    asm volatile("cp.async.wait_group %0;\n" :: "n"(N) : "memory");
}
__device__ __forceinline__ uint32_t smem_u32(const void* p) {
    uint32_t a;
    asm("{ .reg .u64 t; cvta.to.shared.u64 t, %1; cvt.u32.u64 %0, t; }"
        : "=r"(a) : "l"(p));
    return a;
}
__device__ __forceinline__ float tanh_ap(float x) {
    float y;
    asm("tanh.approx.f32 %0, %1;" : "=f"(y) : "f"(x));
    return y;
}
__device__ __forceinline__ void ldsm_x4(uint32_t* r, uint32_t addr) {
    asm volatile("ldmatrix.sync.aligned.m8n8.x4.shared.b16 {%0,%1,%2,%3}, [%4];"
                 : "=r"(r[0]), "=r"(r[1]), "=r"(r[2]), "=r"(r[3]) : "r"(addr));
}
__device__ __forceinline__ void mma_f16(float* c, const uint32_t* a,
                                        uint32_t b0, uint32_t b1) {
    asm volatile(
        "mma.sync.aligned.m16n8k16.row.col.f32.f16.f16.f32 "
        "{%0,%1,%2,%3}, {%4,%5,%6,%7}, {%8,%9}, {%0,%1,%2,%3};"
        : "+f"(c[0]), "+f"(c[1]), "+f"(c[2]), "+f"(c[3])
        : "r"(a[0]), "r"(a[1]), "r"(a[2]), "r"(a[3]), "r"(b0), "r"(b1));
}

// SMEM per CTA (dynamic, 72KB):
//   A16: 3 stages x 16KB  [blk4][row128][32B, 16B-pair xor (r>>2)&1]
//   B16: 3 stages x 8KB   [blk4][n64][32B, xor]
#define SMA_STAGE 16384u
#define SMB_OFF   49152u
#define SMB_STAGE 8192u
#define SMEM_TOTAL (49152 + 3*8192)   // 73728

// ---------------- converts ----------------
__global__ void k_cvt_enc(const float* __restrict__ enc) {
    size_t i = ((size_t)blockIdx.x*blockDim.x + threadIdx.x) * 8;
    const float4* s = reinterpret_cast<const float4*>(enc + i);
    float4 v0 = s[0], v1 = s[1];
    __half2 h[4];
    h[0] = __floats2half2_rn(v0.x, v0.y);
    h[1] = __floats2half2_rn(v0.z, v0.w);
    h[2] = __floats2half2_rn(v1.x, v1.y);
    h[3] = __floats2half2_rn(v1.z, v1.w);
    *reinterpret_cast<uint4*>(g_ench + i) = *reinterpret_cast<uint4*>(h);
}
__global__ void k_cvt_W(const float* __restrict__ W) {
    size_t i = ((size_t)blockIdx.x*blockDim.x + threadIdx.x) * 8;
    const float4* s = reinterpret_cast<const float4*>(W + i);
    float4 v0 = s[0], v1 = s[1];
    __half2 h[4];
    h[0] = __floats2half2_rn(v0.x, v0.y);
    h[1] = __floats2half2_rn(v0.z, v0.w);
    h[2] = __floats2half2_rn(v1.x, v1.y);
    h[3] = __floats2half2_rn(v1.z, v1.w);
    *reinterpret_cast<uint4*>(g_Wh + i) = *reinterpret_cast<uint4*>(h);
}

// ---------------- prep: ubb = U(h) + U_b + W_b ----------------
__global__ void k_ubb(const float* __restrict__ hid,
                      const float* __restrict__ Uw,
                      const float* __restrict__ Ub,
                      const float* __restrict__ Wb) {
    int b = blockIdx.x;
    int h = threadIdx.x;
    __shared__ float hs[Hh];
    hs[h] = hid[b*Hh + h];
    __syncthreads();
    const float4* row = reinterpret_cast<const float4*>(Uw + (size_t)h*Hh);
    const float4* hv  = reinterpret_cast<const float4*>(hs);
    float acc = 0.f;
    #pragma unroll 4
    for (int k = 0; k < Hh/4; k++) {
        float4 r = row[k]; float4 x = hv[k];
        acc += r.x*x.x + r.y*x.y + r.z*x.z + r.w*x.w;
    }
    g_ubb[b*Hh + h] = acc + Ub[h] + Wb[h];
}

// ---------------- main: fp16 mma, 3-stage single-sync pipeline ----------------
// CTA M128xN64, 256 threads / 8 warps, 3 CTAs/SM.
// grid (8 coltiles, 1024 rowtiles): 8 launch-adjacent CTAs share the A tile in L2,
// W (512KB fp16) stays fully L2-resident.

__device__ __forceinline__ void load_chunk(uint32_t sb, int row0, int col0,
                                           int kc, int stage, int tid) {
    uint32_t abase = sb + (uint32_t)stage * SMA_STAGE;
    uint32_t bbase = sb + SMB_OFF + (uint32_t)stage * SMB_STAGE;
    #pragma unroll
    for (int i = 0; i < 4; i++) {            // A: 1024 x 16B
        int u = tid + i*256;
        int blk = u >> 8, v = u & 255, r = v >> 1, c16 = v & 1;
        int p16 = c16 ^ ((r >> 2) & 1);
        cpasync16(abase + (uint32_t)(blk*4096 + r*32 + p16*16),
                  g_ench + (size_t)(row0 + r)*Hh + kc + blk*16 + c16*8);
    }
    #pragma unroll
    for (int i = 0; i < 2; i++) {            // B: 512 x 16B (64 n-rows)
        int u = tid + i*256;
        int blk = u >> 7, v = u & 127, n = v >> 1, c16 = v & 1;
        int p16 = c16 ^ ((n >> 2) & 1);
        cpasync16(bbase + (uint32_t)(blk*2048 + n*32 + p16*16),
                  g_Wh + (size_t)(col0 + n)*Hh + kc + blk*16 + c16*8);
    }
    cp_commit();
}

__global__ void __launch_bounds__(256, 3)
k_energy(const float* __restrict__ Vw) {
    extern __shared__ char smem[];
    uint32_t sb = smem_u32(smem);
    const int tid = threadIdx.x;
    const int wid = tid >> 5, lane = tid & 31;
    const int g = lane >> 2, tig = lane & 3;
    const int warp_m = wid & 3, warp_n = wid >> 2;
    const int m_base = warp_m * 32;
    const int n_base = warp_n * 32;

    const int col0 = blockIdx.x * 64;
    const int row0 = blockIdx.y * 128;       // never spans a batch
    const int b = row0 / Ss;

    // ldmatrix lane addresses (xor-swizzled 16B chunks in 32B rows)
    const int a_row = m_base + (lane & 15);
    const uint32_t a_sw = (uint32_t)(((lane >> 4) ^ (a_row >> 2)) & 1);
    const uint32_t a_off = (uint32_t)(a_row*32) + a_sw*16;
    const int b_nrow = n_base + (lane & 7) + ((lane >> 1) & 8);
    const uint32_t b_sw = (uint32_t)(((lane >> 3) ^ (b_nrow >> 2)) & 1);
    const uint32_t b_off = (uint32_t)(b_nrow*32) + b_sw*16;

    float c[2][4][4];
    #pragma unroll
    for (int mt = 0; mt < 2; mt++)
        #pragma unroll
        for (int nt = 0; nt < 4; nt++)
            #pragma unroll
            for (int j = 0; j < 4; j++) c[mt][nt][j] = 0.f;

    // prologue: chunks 0,1 in flight
    load_chunk(sb, row0, col0, 0,  0, tid);
    load_chunk(sb, row0, col0, 64, 1, tid);

    for (int ch = 0; ch < 8; ch++) {
        if (ch < 7) cp_wait<1>(); else cp_wait<0>();
        __syncthreads();                     // chunk ch ready; MMA(ch-1) done by all

        // hoisted load: stage (ch+2)%3 was last read by MMA(ch-1) -> safe now
        if (ch + 2 < 8)
            load_chunk(sb, row0, col0, (ch + 2)*64, (ch + 2) % 3, tid);

        const uint32_t st = (uint32_t)(ch % 3);
        const uint32_t A16 = sb + st*SMA_STAGE;
        const uint32_t Bs  = sb + SMB_OFF + st*SMB_STAGE;

        #pragma unroll
        for (int blk = 0; blk < 4; blk++) {
            uint32_t a[2][4];
            ldsm_x4(a[0], A16 + blk*4096u + a_off);
            ldsm_x4(a[1], A16 + blk*4096u + a_off + 512u);
            uint32_t bf[4][2];
            #pragma unroll
            for (int p = 0; p < 2; p++) {
                uint32_t r[4];
                ldsm_x4(r, Bs + blk*2048u + b_off + (uint32_t)p*512u);
                bf[2*p][0]   = r[0]; bf[2*p][1]   = r[1];
                bf[2*p+1][0] = r[2]; bf[2*p+1][1] = r[3];
            }
            #pragma unroll
            for (int mt = 0; mt < 2; mt++)
                #pragma unroll
                for (int nt = 0; nt < 4; nt++)
                    mma_f16(c[mt][nt], a[mt], bf[nt][0], bf[nt][1]);
        }
    }

    // fused epilogue: partial energy over this CTA's 64 cols, combined in smem
    __syncthreads();
    float* s_e = reinterpret_cast<float*>(smem);
    if (tid < 128) s_e[tid] = 0.f;
    __syncthreads();

    float ub[4][2], vv[4][2];
    #pragma unroll
    for (int nt = 0; nt < 4; nt++) {
        int cb = col0 + n_base + nt*8 + 2*tig;
        ub[nt][0] = g_ubb[b*Hh + cb];     ub[nt][1] = g_ubb[b*Hh + cb + 1];
        vv[nt][0] = Vw[cb];               vv[nt][1] = Vw[cb + 1];
    }
    #pragma unroll
    for (int mt = 0; mt < 2; mt++) {
        float e0 = 0.f, e1 = 0.f;
        #pragma unroll
        for (int nt = 0; nt < 4; nt++) {
            e0 += vv[nt][0]*tanh_ap(c[mt][nt][0] + ub[nt][0]);
            e0 += vv[nt][1]*tanh_ap(c[mt][nt][1] + ub[nt][1]);
            e1 += vv[nt][0]*tanh_ap(c[mt][nt][2] + ub[nt][0]);
            e1 += vv[nt][1]*tanh_ap(c[mt][nt][3] + ub[nt][1]);
        }
        e0 += __shfl_xor_sync(0xffffffffu, e0, 1);
        e0 += __shfl_xor_sync(0xffffffffu, e0, 2);
        e1 += __shfl_xor_sync(0xffffffffu, e1, 1);
        e1 += __shfl_xor_sync(0xffffffffu, e1, 2);
        if (tig == 0) {
            atomicAdd(&s_e[m_base + mt*16 + g],     e0);
            atomicAdd(&s_e[m_base + mt*16 + g + 8], e1);
        }
    }
    __syncthreads();
    if (tid < 128)
        g_energy8[(size_t)blockIdx.x*BS + row0 + tid] = s_e[tid];
}

// ---------------- softmax over S per batch (sums 8 coltile slices) ----------------
__global__ void k_softmax(float* __restrict__ attn) {
    const int b = blockIdx.x;
    const int tid = threadIdx.x;             // 256
    __shared__ float red[256];
    float v[8];
    float mx = -1e30f;
    #pragma unroll
    for (int i = 0; i < 8; i++) {
        int idx = b*Ss + tid + i*256;
        float s = 0.f;
        #pragma unroll
        for (int t = 0; t < 8; t++) s += g_energy8[(size_t)t*BS + idx];
        v[i] = s;
        mx = fmaxf(mx, v[i]);
    }
    red[tid] = mx; __syncthreads();
    for (int o = 128; o > 0; o >>= 1) {
        if (tid < o) red[tid] = fmaxf(red[tid], red[tid+o]);
        __syncthreads();
    }
    mx = red[0]; __syncthreads();
    float sum = 0.f;
    #pragma unroll
    for (int i = 0; i < 8; i++) { v[i] = __expf(v[i] - mx); sum += v[i]; }
    red[tid] = sum; __syncthreads();
    for (int o = 128; o > 0; o >>= 1) {
        if (tid < o) red[tid] += red[tid+o];
        __syncthreads();
    }
    float inv = 1.f / red[0];
    #pragma unroll
    for (int i = 0; i < 8; i++)
        attn[b*Ss + tid + i*256] = v[i] * inv;
}

// ---------------- context = attn @ enc (fp16 enc, fp32 accumulate) ----------------
__global__ void k_ctx_part(const float* __restrict__ attn) {
    const int sc = blockIdx.x;               // 0..15
    const int b  = blockIdx.y;
    const int tid = threadIdx.x;             // 256 = 4 grp x 64
    const int grp = tid >> 6;
    const int h0 = (tid & 63) * 8;
    const int s0 = sc * 128;
    const float* ab = attn + b*Ss + s0;
    const __half* eb = g_ench + ((size_t)(b*Ss + s0))*Hh + h0;
    float acc[8] = {0.f,0.f,0.f,0.f,0.f,0.f,0.f,0.f};
    #pragma unroll 4
    for (int i = 0; i < 32; i++) {
        int s = i*4 + grp;
        float w = ab[s];
        uint4 raw = *reinterpret_cast<const uint4*>(eb + (size_t)s*Hh);
        const __half2* hp = reinterpret_cast<const __half2*>(&raw);
        #pragma unroll
        for (int j = 0; j < 4; j++) {
            float2 f = __half22float2(hp[j]);
            acc[2*j]   += w * f.x;
            acc[2*j+1] += w * f.y;
        }
    }
    float* dst = g_ctx + ((size_t)(b*64 + sc*4 + grp))*Hh + h0;
    #pragma unroll
    for (int j = 0; j < 8; j++) dst[j] = acc[j];
}

__global__ void k_ctx_reduce(float* __restrict__ ctx) {
    const int b = blockIdx.x;
    const int h = threadIdx.x;               // 512
    float s = 0.f;
    #pragma unroll
    for (int p = 0; p < 64; p++)
        s += g_ctx[((size_t)(b*64 + p))*Hh + h];
    ctx[b*Hh + h] = s;
}

// ---------------- launch ----------------
extern "C" void kernel_launch(void* const* d_in, const int* in_sizes, int n_in,
                              void* d_out, int out_size) {
    const float* hidden = (const float*)d_in[0];
    const float* enc    = (const float*)d_in[1];
    const float* U_w    = (const float*)d_in[2];
    const float* U_b    = (const float*)d_in[3];
    const float* W_w    = (const float*)d_in[4];
    const float* W_b    = (const float*)d_in[5];
    const float* V_w    = (const float*)d_in[6];
    // V_b shifts all energies equally -> softmax invariant -> unused.

    float* out_ctx  = (float*)d_out;            // [B,H]
    float* out_attn = out_ctx + Bb*Hh;          // [B,S]

    cudaFuncSetAttribute(k_energy,
                         cudaFuncAttributeMaxDynamicSharedMemorySize, SMEM_TOTAL);

    unsigned cvt_blocks = (unsigned)(((size_t)BS * Hh) / 8u / 256u);  // 32768
    k_cvt_enc<<<cvt_blocks, 256>>>(enc);
    k_cvt_W<<<Hh*Hh/8/256, 256>>>(W_w);
    k_ubb<<<Bb, Hh>>>(hidden, U_w, U_b, W_b);
    k_energy<<<dim3(8, BS/128), 256, SMEM_TOTAL>>>(V_w);
    k_softmax<<<Bb, 256>>>(out_attn);
    k_ctx_part<<<dim3(16, Bb), 256>>>(out_attn);
    k_ctx_reduce<<<Bb, Hh>>>(out_ctx);
}

// round 17
// speedup vs baseline: 1.0570x; 1.0046x over previous
#include <cuda_runtime.h>
#include <cuda_fp16.h>
#include <cstdint>

#define Hh 512
#define Bb 64
#define Ss 2048
#define BS (Bb*Ss)   // 131072 rows

// ---------------- device scratch (no cudaMalloc allowed) ----------------
__device__ __half g_ench[(size_t)BS*Hh];   // enc in fp16 (128 MB)
__device__ __half g_Wh[Hh*Hh];             // W_w in fp16
__device__ float g_ubb[Bb*Hh];             // u + U_b + W_b per (b,h)
__device__ float g_energy8[8*BS];          // per-coltile energy partials
__device__ float g_ctx[Bb*32*Hh];          // context partials (16 sc x 2 grp)

// ---------------- generic PTX helpers ----------------
__device__ __forceinline__ void cpasync16(uint32_t dst, const void* src) {
    asm volatile("cp.async.cg.shared.global [%0], [%1], 16;\n"
                 :: "r"(dst), "l"(src));
}
__device__ __forceinline__ void cp_commit() {
    asm volatile("cp.async.commit_group;\n" ::: "memory");
}
template<int N> __device__ __forceinline__ void cp_wait() {
    asm volatile("cp.async.wait_group %0;\n" :: "n"(N) : "memory");
}
__device__ __forceinline__ uint32_t smem_u32(const void* p) {
    uint32_t a;
    asm("{ .reg .u64 t; cvta.to.shared.u64 t, %1; cvt.u32.u64 %0, t; }"
        : "=r"(a) : "l"(p));
    return a;
}
__device__ __forceinline__ float tanh_ap(float x) {
    float y;
    asm("tanh.approx.f32 %0, %1;" : "=f"(y) : "f"(x));
    return y;
}
__device__ __forceinline__ void ldsm_x4(uint32_t* r, uint32_t addr) {
    asm volatile("ldmatrix.sync.aligned.m8n8.x4.shared.b16 {%0,%1,%2,%3}, [%4];"
                 : "=r"(r[0]), "=r"(r[1]), "=r"(r[2]), "=r"(r[3]) : "r"(addr));
}
__device__ __forceinline__ void mma_f16(float* c, const uint32_t* a,
                                        uint32_t b0, uint32_t b1) {
    asm volatile(
        "mma.sync.aligned.m16n8k16.row.col.f32.f16.f16.f32 "
        "{%0,%1,%2,%3}, {%4,%5,%6,%7}, {%8,%9}, {%0,%1,%2,%3};"
        : "+f"(c[0]), "+f"(c[1]), "+f"(c[2]), "+f"(c[3])
        : "r"(a[0]), "r"(a[1]), "r"(a[2]), "r"(a[3]), "r"(b0), "r"(b1));
}

// SMEM per CTA (dynamic, 72KB):
//   A16: 3 stages x 16KB  [blk4][row128][32B, 16B-pair xor (r>>2)&1]
//   B16: 3 stages x 8KB   [blk4][n64][32B, xor]
#define SMA_STAGE 16384u
#define SMB_OFF   49152u
#define SMB_STAGE 8192u
#define SMEM_TOTAL (49152 + 3*8192)   // 73728

// ---------------- converts ----------------
__global__ void k_cvt_enc(const float* __restrict__ enc) {
    size_t i = ((size_t)blockIdx.x*blockDim.x + threadIdx.x) * 8;
    const float4* s = reinterpret_cast<const float4*>(enc + i);
    float4 v0 = s[0], v1 = s[1];
    __half2 h[4];
    h[0] = __floats2half2_rn(v0.x, v0.y);
    h[1] = __floats2half2_rn(v0.z, v0.w);
    h[2] = __floats2half2_rn(v1.x, v1.y);
    h[3] = __floats2half2_rn(v1.z, v1.w);
    *reinterpret_cast<uint4*>(g_ench + i) = *reinterpret_cast<uint4*>(h);
}
__global__ void k_cvt_W(const float* __restrict__ W) {
    size_t i = ((size_t)blockIdx.x*blockDim.x + threadIdx.x) * 8;
    const float4* s = reinterpret_cast<const float4*>(W + i);
    float4 v0 = s[0], v1 = s[1];
    __half2 h[4];
    h[0] = __floats2half2_rn(v0.x, v0.y);
    h[1] = __floats2half2_rn(v0.z, v0.w);
    h[2] = __floats2half2_rn(v1.x, v1.y);
    h[3] = __floats2half2_rn(v1.z, v1.w);
    *reinterpret_cast<uint4*>(g_Wh + i) = *reinterpret_cast<uint4*>(h);
}

// ---------------- prep: ubb = U(h) + U_b + W_b ----------------
__global__ void k_ubb(const float* __restrict__ hid,
                      const float* __restrict__ Uw,
                      const float* __restrict__ Ub,
                      const float* __restrict__ Wb) {
    int b = blockIdx.x;
    int h = threadIdx.x;
    __shared__ float hs[Hh];
    hs[h] = hid[b*Hh + h];
    __syncthreads();
    const float4* row = reinterpret_cast<const float4*>(Uw + (size_t)h*Hh);
    const float4* hv  = reinterpret_cast<const float4*>(hs);
    float acc = 0.f;
    #pragma unroll 4
    for (int k = 0; k < Hh/4; k++) {
        float4 r = row[k]; float4 x = hv[k];
        acc += r.x*x.x + r.y*x.y + r.z*x.z + r.w*x.w;
    }
    g_ubb[b*Hh + h] = acc + Ub[h] + Wb[h];
}

// ---------------- main: fp16 mma, 3-stage single-sync pipeline ----------------
// CTA M128xN64, 256 threads / 8 warps, 3 CTAs/SM.
// grid (8 coltiles, 1024 rowtiles): 8 launch-adjacent CTAs share the A tile in L2,
// W (512KB fp16) stays fully L2-resident.

__device__ __forceinline__ void load_chunk(uint32_t sb, int row0, int col0,
                                           int kc, int stage, int tid) {
    uint32_t abase = sb + (uint32_t)stage * SMA_STAGE;
    uint32_t bbase = sb + SMB_OFF + (uint32_t)stage * SMB_STAGE;
    #pragma unroll
    for (int i = 0; i < 4; i++) {            // A: 1024 x 16B
        int u = tid + i*256;
        int blk = u >> 8, v = u & 255, r = v >> 1, c16 = v & 1;
        int p16 = c16 ^ ((r >> 2) & 1);
        cpasync16(abase + (uint32_t)(blk*4096 + r*32 + p16*16),
                  g_ench + (size_t)(row0 + r)*Hh + kc + blk*16 + c16*8);
    }
    #pragma unroll
    for (int i = 0; i < 2; i++) {            // B: 512 x 16B (64 n-rows)
        int u = tid + i*256;
        int blk = u >> 7, v = u & 127, n = v >> 1, c16 = v & 1;
        int p16 = c16 ^ ((n >> 2) & 1);
        cpasync16(bbase + (uint32_t)(blk*2048 + n*32 + p16*16),
                  g_Wh + (size_t)(col0 + n)*Hh + kc + blk*16 + c16*8);
    }
    cp_commit();
}

__global__ void __launch_bounds__(256, 3)
k_energy(const float* __restrict__ Vw) {
    extern __shared__ char smem[];
    uint32_t sb = smem_u32(smem);
    const int tid = threadIdx.x;
    const int wid = tid >> 5, lane = tid & 31;
    const int g = lane >> 2, tig = lane & 3;
    const int warp_m = wid & 3, warp_n = wid >> 2;
    const int m_base = warp_m * 32;
    const int n_base = warp_n * 32;

    const int col0 = blockIdx.x * 64;
    const int row0 = blockIdx.y * 128;       // never spans a batch
    const int b = row0 / Ss;

    // ldmatrix lane addresses (xor-swizzled 16B chunks in 32B rows)
    const int a_row = m_base + (lane & 15);
    const uint32_t a_sw = (uint32_t)(((lane >> 4) ^ (a_row >> 2)) & 1);
    const uint32_t a_off = (uint32_t)(a_row*32) + a_sw*16;
    const int b_nrow = n_base + (lane & 7) + ((lane >> 1) & 8);
    const uint32_t b_sw = (uint32_t)(((lane >> 3) ^ (b_nrow >> 2)) & 1);
    const uint32_t b_off = (uint32_t)(b_nrow*32) + b_sw*16;

    float c[2][4][4];
    #pragma unroll
    for (int mt = 0; mt < 2; mt++)
        #pragma unroll
        for (int nt = 0; nt < 4; nt++)
            #pragma unroll
            for (int j = 0; j < 4; j++) c[mt][nt][j] = 0.f;

    // prologue: chunks 0,1 in flight
    load_chunk(sb, row0, col0, 0,  0, tid);
    load_chunk(sb, row0, col0, 64, 1, tid);

    for (int ch = 0; ch < 8; ch++) {
        if (ch < 7) cp_wait<1>(); else cp_wait<0>();
        __syncthreads();                     // chunk ch ready; MMA(ch-1) done by all

        // hoisted load: stage (ch+2)%3 was last read by MMA(ch-1) -> safe now
        if (ch + 2 < 8)
            load_chunk(sb, row0, col0, (ch + 2)*64, (ch + 2) % 3, tid);

        const uint32_t st = (uint32_t)(ch % 3);
        const uint32_t A16 = sb + st*SMA_STAGE;
        const uint32_t Bs  = sb + SMB_OFF + st*SMB_STAGE;

        #pragma unroll
        for (int blk = 0; blk < 4; blk++) {
            uint32_t a[2][4];
            ldsm_x4(a[0], A16 + blk*4096u + a_off);
            ldsm_x4(a[1], A16 + blk*4096u + a_off + 512u);
            uint32_t bf[4][2];
            #pragma unroll
            for (int p = 0; p < 2; p++) {
                uint32_t r[4];
                ldsm_x4(r, Bs + blk*2048u + b_off + (uint32_t)p*512u);
                bf[2*p][0]   = r[0]; bf[2*p][1]   = r[1];
                bf[2*p+1][0] = r[2]; bf[2*p+1][1] = r[3];
            }
            #pragma unroll
            for (int mt = 0; mt < 2; mt++)
                #pragma unroll
                for (int nt = 0; nt < 4; nt++)
                    mma_f16(c[mt][nt], a[mt], bf[nt][0], bf[nt][1]);
        }
    }

    // fused epilogue: partial energy over this CTA's 64 cols, combined in smem
    __syncthreads();
    float* s_e = reinterpret_cast<float*>(smem);
    if (tid < 128) s_e[tid] = 0.f;
    __syncthreads();

    float ub[4][2], vv[4][2];
    #pragma unroll
    for (int nt = 0; nt < 4; nt++) {
        int cb = col0 + n_base + nt*8 + 2*tig;
        ub[nt][0] = g_ubb[b*Hh + cb];     ub[nt][1] = g_ubb[b*Hh + cb + 1];
        vv[nt][0] = Vw[cb];               vv[nt][1] = Vw[cb + 1];
    }
    #pragma unroll
    for (int mt = 0; mt < 2; mt++) {
        float e0 = 0.f, e1 = 0.f;
        #pragma unroll
        for (int nt = 0; nt < 4; nt++) {
            e0 += vv[nt][0]*tanh_ap(c[mt][nt][0] + ub[nt][0]);
            e0 += vv[nt][1]*tanh_ap(c[mt][nt][1] + ub[nt][1]);
            e1 += vv[nt][0]*tanh_ap(c[mt][nt][2] + ub[nt][0]);
            e1 += vv[nt][1]*tanh_ap(c[mt][nt][3] + ub[nt][1]);
        }
        e0 += __shfl_xor_sync(0xffffffffu, e0, 1);
        e0 += __shfl_xor_sync(0xffffffffu, e0, 2);
        e1 += __shfl_xor_sync(0xffffffffu, e1, 1);
        e1 += __shfl_xor_sync(0xffffffffu, e1, 2);
        if (tig == 0) {
            atomicAdd(&s_e[m_base + mt*16 + g],     e0);
            atomicAdd(&s_e[m_base + mt*16 + g + 8], e1);
        }
    }
    __syncthreads();
    if (tid < 128)
        g_energy8[(size_t)blockIdx.x*BS + row0 + tid] = s_e[tid];
}

// ---------------- softmax over S per batch (sums 8 coltile slices) ----------------
__global__ void k_softmax(float* __restrict__ attn) {
    const int b = blockIdx.x;
    const int tid = threadIdx.x;             // 256
    __shared__ float red[256];
    float v[8];
    float mx = -1e30f;
    #pragma unroll
    for (int i = 0; i < 8; i++) {
        int idx = b*Ss + tid + i*256;
        float s = 0.f;
        #pragma unroll
        for (int t = 0; t < 8; t++) s += g_energy8[(size_t)t*BS + idx];
        v[i] = s;
        mx = fmaxf(mx, v[i]);
    }
    red[tid] = mx; __syncthreads();
    for (int o = 128; o > 0; o >>= 1) {
        if (tid < o) red[tid] = fmaxf(red[tid], red[tid+o]);
        __syncthreads();
    }
    mx = red[0]; __syncthreads();
    float sum = 0.f;
    #pragma unroll
    for (int i = 0; i < 8; i++) { v[i] = __expf(v[i] - mx); sum += v[i]; }
    red[tid] = sum; __syncthreads();
    for (int o = 128; o > 0; o >>= 1) {
        if (tid < o) red[tid] += red[tid+o];
        __syncthreads();
    }
    float inv = 1.f / red[0];
    #pragma unroll
    for (int i = 0; i < 8; i++)
        attn[b*Ss + tid + i*256] = v[i] * inv;
}

// ---------------- context = attn @ enc (fp16 enc, fp32 accumulate) ----------------
// 256 threads = 2 grp x 128; each thread: h-chunk of 8, two interleaved s-streams
// (s = i*4 + grp*2 + {0,1}) -> 2 independent load chains, MLP ~= 2x unroll.
__global__ void k_ctx_part(const float* __restrict__ attn) {
    const int sc = blockIdx.x;               // 0..15
    const int b  = blockIdx.y;
    const int tid = threadIdx.x;             // 256 = 2 grp x 128... map: grp = tid>>7
    const int grp = tid >> 7;                // 0..1
    const int hq = tid & 63;                 // 64 h-chunks of 8
    const int half = (tid >> 6) & 1;         // unused h split? no: 128 threads per grp
    // 128 threads per grp: h0 = (tid & 127) * 4  -> 4 halfs per thread? Keep 8-wide:
    // simpler: 2 grps x 128 threads, each thread handles h-chunk of 4 (128*4=512)
    const int h0 = (tid & 127) * 4;
    const int s0 = sc * 128;
    const float* ab = attn + b*Ss + s0;
    const __half* eb = g_ench + ((size_t)(b*Ss + s0))*Hh + h0;
    float acc[4] = {0.f, 0.f, 0.f, 0.f};
    #pragma unroll 8
    for (int i = 0; i < 64; i++) {
        int s = i*2 + grp;
        float w = ab[s];
        uint2 raw = *reinterpret_cast<const uint2*>(eb + (size_t)s*Hh);
        const __half2* hp = reinterpret_cast<const __half2*>(&raw);
        float2 f0 = __half22float2(hp[0]);
        float2 f1 = __half22float2(hp[1]);
        acc[0] += w * f0.x;  acc[1] += w * f0.y;
        acc[2] += w * f1.x;  acc[3] += w * f1.y;
    }
    (void)hq; (void)half;
    float* dst = g_ctx + ((size_t)(b*32 + sc*2 + grp))*Hh + h0;
    #pragma unroll
    for (int j = 0; j < 4; j++) dst[j] = acc[j];
}

__global__ void k_ctx_reduce(float* __restrict__ ctx) {
    const int b = blockIdx.x;
    const int h = threadIdx.x;               // 512
    float s = 0.f;
    #pragma unroll
    for (int p = 0; p < 32; p++)
        s += g_ctx[((size_t)(b*32 + p))*Hh + h];
    ctx[b*Hh + h] = s;
}

// ---------------- launch ----------------
extern "C" void kernel_launch(void* const* d_in, const int* in_sizes, int n_in,
                              void* d_out, int out_size) {
    const float* hidden = (const float*)d_in[0];
    const float* enc    = (const float*)d_in[1];
    const float* U_w    = (const float*)d_in[2];
    const float* U_b    = (const float*)d_in[3];
    const float* W_w    = (const float*)d_in[4];
    const float* W_b    = (const float*)d_in[5];
    const float* V_w    = (const float*)d_in[6];
    // V_b shifts all energies equally -> softmax invariant -> unused.

    float* out_ctx  = (float*)d_out;            // [B,H]
    float* out_attn = out_ctx + Bb*Hh;          // [B,S]

    cudaFuncSetAttribute(k_energy,
                         cudaFuncAttributeMaxDynamicSharedMemorySize, SMEM_TOTAL);

    unsigned cvt_blocks = (unsigned)(((size_t)BS * Hh) / 8u / 256u);  // 32768
    k_cvt_enc<<<cvt_blocks, 256>>>(enc);
    k_cvt_W<<<Hh*Hh/8/256, 256>>>(W_w);
    k_ubb<<<Bb, Hh>>>(hidden, U_w, U_b, W_b);
    k_energy<<<dim3(8, BS/128), 256, SMEM_TOTAL>>>(V_w);
    k_softmax<<<Bb, 256>>>(out_attn);
    k_ctx_part<<<dim3(16, Bb), 256>>>(out_attn);
    k_ctx_reduce<<<Bb, Hh>>>(out_ctx);
}